// round 5
// baseline (speedup 1.0000x reference)
#include <cuda_runtime.h>
#include <math.h>
#include <stdint.h>

// ---------------- problem dims ----------------
#define TT 128
#define NN 1024
#define HH 512
#define II 64
#define G3 1536            // 3*HH

// ---------------- device scratch ----------------
__device__ float g_Whh_t[8 * 192 * HH];          // strip-ordered, tf32-rounded
__device__ float g_Wih_t[G3 * II];               // tf32-rounded
__device__ float g_hA[2][NN * HH];               // tf32 h ping-pong (A operand)
__device__ float g_Gi[(size_t)TT * NN * G3];     // precomputed x @ W_ih^T (805 MB)

// ---------------- helpers ----------------
__device__ __forceinline__ uint32_t f2tf32(float f) {
    uint32_t r;
    asm("cvt.rna.tf32.f32 %0, %1;" : "=r"(r) : "f"(f));
    return r;
}
__device__ __forceinline__ uint32_t smem_u32(const void* p) {
    uint32_t a;
    asm("{ .reg .u64 t; cvta.to.shared.u64 t, %1; cvt.u32.u64 %0, t; }" : "=r"(a) : "l"(p));
    return a;
}
__device__ __forceinline__ float sigf(float x) {
    return 1.0f / (1.0f + __expf(-x));
}

#define CP_ASYNC16(dst, src) \
    asm volatile("cp.async.cg.shared.global [%0], [%1], 16;" :: "r"(dst), "l"(src))
#define CP_COMMIT() asm volatile("cp.async.commit_group;" ::: "memory")

__device__ __forceinline__ void mma_tf32(float (&c)[4], const uint32_t (&a)[4],
                                         const uint32_t (&b)[2]) {
    asm volatile(
        "mma.sync.aligned.m16n8k8.row.col.f32.tf32.tf32.f32 "
        "{%0,%1,%2,%3}, {%4,%5,%6,%7}, {%8,%9}, {%0,%1,%2,%3};"
        : "+f"(c[0]), "+f"(c[1]), "+f"(c[2]), "+f"(c[3])
        : "r"(a[0]), "r"(a[1]), "r"(a[2]), "r"(a[3]), "r"(b[0]), "r"(b[1]));
}

// ================= prep: tf32-round weights (strip layout) + hxs =================
__global__ void prep_kernel(const float* __restrict__ W_hh,
                            const float* __restrict__ W_ih,
                            const float* __restrict__ hxs) {
    int idx = blockIdx.x * blockDim.x + threadIdx.x;
    if (idx < G3 * HH) {
        int r = idx >> 9, k = idx & 511;
        int g = r >> 9, u = r & 511, s = u >> 6, c = u & 63;
        g_Whh_t[((size_t)(s * 192 + (g << 6) + c)) * HH + k] =
            __uint_as_float(f2tf32(W_hh[idx]));
    }
    if (idx < G3 * II) g_Wih_t[idx] = __uint_as_float(f2tf32(W_ih[idx]));
    if (idx < NN * HH) g_hA[0][idx] = __uint_as_float(f2tf32(hxs[idx]));
}

// ================= Gi precompute: Gi[T*N, 1536] = X[T*N,64] @ W_ih^T =============
#define GI_SST 68
__global__ __launch_bounds__(256, 1)
void gi_kernel(const float* __restrict__ X) {
    extern __shared__ float sm[];
    float* Xs = sm;                    // [128][GI_SST]
    float* Ws = sm + 128 * GI_SST;     // [128][GI_SST]
    const int tid = threadIdx.x;
    const int rb = blockIdx.y * 128;
    const int cb = blockIdx.x * 128;

    #pragma unroll
    for (int it = 0; it < 8; it++) {
        int id = it * 256 + tid;           // 0..2047 float4 slots
        int row = id >> 4, c4 = (id & 15) * 4;
        float4 v = *reinterpret_cast<const float4*>(X + (size_t)(rb + row) * II + c4);
        uint4 o = make_uint4(f2tf32(v.x), f2tf32(v.y), f2tf32(v.z), f2tf32(v.w));
        *reinterpret_cast<uint4*>(Xs + row * GI_SST + c4) = o;
        float4 w = *reinterpret_cast<const float4*>(g_Wih_t + (size_t)(cb + row) * II + c4);
        *reinterpret_cast<float4*>(Ws + row * GI_SST + c4) = w;
    }
    __syncthreads();

    const int w = tid >> 5, lane = tid & 31, g = lane >> 2, t = lane & 3;
    const int wr = w & 3, wc = w >> 2;   // 4 row groups x 2 col groups
    float acc[2][8][4];
    #pragma unroll
    for (int sl = 0; sl < 2; sl++)
        #pragma unroll
        for (int j = 0; j < 8; j++)
            #pragma unroll
            for (int q = 0; q < 4; q++) acc[sl][j][q] = 0.0f;

    #pragma unroll
    for (int k8 = 0; k8 < 8; k8++) {
        const int kb = k8 * 8;
        uint32_t a[2][4], b[8][2];
        #pragma unroll
        for (int sl = 0; sl < 2; sl++) {
            int m0 = wr * 32 + sl * 16;
            a[sl][0] = __float_as_uint(Xs[(m0 + g) * GI_SST + kb + t]);
            a[sl][1] = __float_as_uint(Xs[(m0 + 8 + g) * GI_SST + kb + t]);
            a[sl][2] = __float_as_uint(Xs[(m0 + g) * GI_SST + kb + t + 4]);
            a[sl][3] = __float_as_uint(Xs[(m0 + 8 + g) * GI_SST + kb + t + 4]);
        }
        #pragma unroll
        for (int j = 0; j < 8; j++) {
            int n0 = wc * 64 + j * 8;
            b[j][0] = __float_as_uint(Ws[(n0 + g) * GI_SST + kb + t]);
            b[j][1] = __float_as_uint(Ws[(n0 + g) * GI_SST + kb + t + 4]);
        }
        #pragma unroll
        for (int sl = 0; sl < 2; sl++)
            #pragma unroll
            for (int j = 0; j < 8; j++) mma_tf32(acc[sl][j], a[sl], b[j]);
    }

    #pragma unroll
    for (int sl = 0; sl < 2; sl++) {
        #pragma unroll
        for (int j = 0; j < 8; j++) {
            int row = rb + wr * 32 + sl * 16 + g;
            int col = cb + wc * 64 + j * 8 + 2 * t;
            *reinterpret_cast<float2*>(g_Gi + (size_t)row * G3 + col) =
                make_float2(acc[sl][j][0], acc[sl][j][1]);
            *reinterpret_cast<float2*>(g_Gi + (size_t)(row + 8) * G3 + col) =
                make_float2(acc[sl][j][2], acc[sl][j][3]);
        }
    }
}

// ================= per-step kernel: S = h @ W_hh^T, gates, h_new =================
#define NTH 512
#define SAST 36
#define ABUF_B (64 * SAST * 4)            // 9216
#define BBUF_B (192 * SAST * 4)           // 27648
#define STAGE_B (ABUF_B + BBUF_B)         // 36864
#define PIPE_B  (3 * STAGE_B)             // 110592
// epilogue smem region (after pipeline buffers)
#define EPI_GI  PIPE_B                    // [64][192] f32 = 49152
#define EPI_HP  (EPI_GI + 49152)          // [64][64]  f32 = 16384
#define EPI_BI  (EPI_HP + 16384)          // [192] f32 = 768
#define EPI_BH  (EPI_BI + 768)            // [192] f32 = 768
#define EPI_M   (EPI_BH + 768)            // [64]  f32 = 256
#define SMEM_STEP (EPI_M + 256)           // 177920
#define SST 200
#define NSTG 16

__device__ __forceinline__ void issue_stage(int stg, uint32_t sbase,
                                            const float* __restrict__ hA,
                                            int rb, int strip, int tid) {
    const int k0 = stg * 32;
    const uint32_t abase = sbase + (stg % 3) * STAGE_B;
    {
        int row = tid >> 3, c = tid & 7;       // 512 slots, 1 per thread
        CP_ASYNC16(abase + row * (SAST * 4) + c * 16,
                   hA + (size_t)(rb + row) * HH + k0 + c * 4);
    }
    const uint32_t bbase = abase + ABUF_B;
    const float* wsrc = g_Whh_t + (size_t)strip * 192 * HH + k0;
    #pragma unroll
    for (int it = 0; it < 3; it++) {
        int id = it * NTH + tid;               // 0..1535
        int row = id >> 3, c = id & 7;
        CP_ASYNC16(bbase + row * (SAST * 4) + c * 16,
                   wsrc + (size_t)row * HH + c * 4);
    }
}

__global__ __launch_bounds__(NTH, 1)
void gru_step(const float* __restrict__ hA,       // tf32 h (prev), [NN,HH]
              float* __restrict__ hA_next,        // tf32 h (new)
              const float* __restrict__ h_prev,   // fp32 h (prev)
              const float* __restrict__ m_t,      // [NN]
              const float* __restrict__ Gi_t,     // [NN, G3]
              const float* __restrict__ b_ih,
              const float* __restrict__ b_hh,
              float* __restrict__ h_out,
              float* __restrict__ h_out2) {
    extern __shared__ char smem[];
    const uint32_t sbase = smem_u32(smem);
    const int tid = threadIdx.x;
    const int strip = blockIdx.x;             // 0..7 -> gate cols strip*64..
    const int rb = blockIdx.y * 64;

    const int w = tid >> 5, lane = tid & 31, g = lane >> 2, t = lane & 3;
    const int wr = w & 3, wc = w >> 2;        // 4 row groups (16) x 4 col groups (48)

    float acc[6][4];
    #pragma unroll
    for (int j = 0; j < 6; j++)
        #pragma unroll
        for (int q = 0; q < 4; q++) acc[j][q] = 0.0f;

    issue_stage(0, sbase, hA, rb, strip, tid); CP_COMMIT();
    issue_stage(1, sbase, hA, rb, strip, tid); CP_COMMIT();

    // ---- epilogue-data prefetch (own commit group; overlapped with mainloop) ----
    {
        // Gi tile: 64 rows x 192 cols -> [64][192] gate-major (g*64 + hcol)
        #pragma unroll
        for (int it = 0; it < 6; it++) {
            int id = it * NTH + tid;           // 0..3071 float4 slots
            int row = id / 48, c4 = (id % 48) * 4;
            int gg = c4 >> 6, hc = c4 & 63;
            CP_ASYNC16(sbase + EPI_GI + (row * 192 + c4) * 4,
                       Gi_t + (size_t)(rb + row) * G3 + gg * HH + strip * 64 + hc);
        }
        // h_prev tile: 64 x 64
        #pragma unroll
        for (int it = 0; it < 2; it++) {
            int id = it * NTH + tid;           // 0..1023
            int row = id >> 4, c4 = (id & 15) * 4;
            CP_ASYNC16(sbase + EPI_HP + (row * 64 + c4) * 4,
                       h_prev + (size_t)(rb + row) * HH + strip * 64 + c4);
        }
        if (tid < 48) {       // b_ih slice, gate-major [192]
            int c4 = tid * 4, gg = c4 >> 6, hc = c4 & 63;
            CP_ASYNC16(sbase + EPI_BI + c4 * 4, b_ih + gg * HH + strip * 64 + hc);
        } else if (tid < 96) {
            int c4 = (tid - 48) * 4, gg = c4 >> 6, hc = c4 & 63;
            CP_ASYNC16(sbase + EPI_BH + c4 * 4, b_hh + gg * HH + strip * 64 + hc);
        } else if (tid < 112) {
            int c4 = (tid - 96) * 4;
            CP_ASYNC16(sbase + EPI_M + c4 * 4, m_t + rb + c4);
        }
        CP_COMMIT();
    }

    for (int stg = 0; stg < NSTG; stg++) {
        if (stg < NSTG - 2) asm volatile("cp.async.wait_group 1;" ::: "memory");
        else                asm volatile("cp.async.wait_group 0;" ::: "memory");
        __syncthreads();
        if (stg + 2 < NSTG) { issue_stage(stg + 2, sbase, hA, rb, strip, tid); CP_COMMIT(); }

        const float* As = (const float*)(smem + (stg % 3) * STAGE_B);
        const float* Bs = (const float*)(smem + (stg % 3) * STAGE_B + ABUF_B);
        #pragma unroll
        for (int k8 = 0; k8 < 4; k8++) {
            const int kb = k8 * 8;
            uint32_t a[4], b[6][2];
            {
                int m0 = wr * 16;
                a[0] = __float_as_uint(As[(m0 + g) * SAST + kb + t]);
                a[1] = __float_as_uint(As[(m0 + 8 + g) * SAST + kb + t]);
                a[2] = __float_as_uint(As[(m0 + g) * SAST + kb + t + 4]);
                a[3] = __float_as_uint(As[(m0 + 8 + g) * SAST + kb + t + 4]);
            }
            #pragma unroll
            for (int j = 0; j < 6; j++) {
                int n0 = wc * 48 + j * 8;
                b[j][0] = __float_as_uint(Bs[(n0 + g) * SAST + kb + t]);
                b[j][1] = __float_as_uint(Bs[(n0 + g) * SAST + kb + t + 4]);
            }
            #pragma unroll
            for (int j = 0; j < 6; j++) mma_tf32(acc[j], a, b[j]);
        }
    }

    // ---- stage S through smem so each thread sees r,z,n of its output cols ----
    __syncthreads();
    float* Ssh = (float*)smem;   // [64][SST], reuses pipeline buffers only
    #pragma unroll
    for (int j = 0; j < 6; j++) {
        int r0 = wr * 16 + g;
        int c0 = wc * 48 + j * 8 + 2 * t;
        *reinterpret_cast<float2*>(&Ssh[r0 * SST + c0]) =
            make_float2(acc[j][0], acc[j][1]);
        *reinterpret_cast<float2*>(&Ssh[(r0 + 8) * SST + c0]) =
            make_float2(acc[j][2], acc[j][3]);
    }
    __syncthreads();

    // ---- gates + mask + store (thread: 1 row x 8 cols) ----
    {
        const float* sGi = (const float*)(smem + EPI_GI);
        const float* sHp = (const float*)(smem + EPI_HP);
        const float* sBi = (const float*)(smem + EPI_BI);
        const float* sBh = (const float*)(smem + EPI_BH);
        const float* sM  = (const float*)(smem + EPI_M);

        const int row_l = tid >> 3;
        const int cb_l = (tid & 7) * 8;
        const int grow = rb + row_l;
        const int gcol0 = strip * 64 + cb_l;
        const float m = sM[row_l];
        float* o1 = h_out + (size_t)grow * HH + gcol0;
        float* o2 = h_out2 ? h_out2 + (size_t)grow * HH + gcol0 : nullptr;
        float* oa = hA_next + (size_t)grow * HH + gcol0;

        #pragma unroll
        for (int q = 0; q < 2; q++) {
            const int c = cb_l + q * 4;
            float4 Sr = *reinterpret_cast<const float4*>(&Ssh[row_l * SST + c]);
            float4 Sz = *reinterpret_cast<const float4*>(&Ssh[row_l * SST + 64 + c]);
            float4 Sn = *reinterpret_cast<const float4*>(&Ssh[row_l * SST + 128 + c]);
            float4 Gr = *reinterpret_cast<const float4*>(&sGi[row_l * 192 + c]);
            float4 Gz = *reinterpret_cast<const float4*>(&sGi[row_l * 192 + 64 + c]);
            float4 Gn = *reinterpret_cast<const float4*>(&sGi[row_l * 192 + 128 + c]);
            float4 br1 = *reinterpret_cast<const float4*>(&sBi[c]);
            float4 bz1 = *reinterpret_cast<const float4*>(&sBi[64 + c]);
            float4 bn1 = *reinterpret_cast<const float4*>(&sBi[128 + c]);
            float4 br2 = *reinterpret_cast<const float4*>(&sBh[c]);
            float4 bz2 = *reinterpret_cast<const float4*>(&sBh[64 + c]);
            float4 bn2 = *reinterpret_cast<const float4*>(&sBh[128 + c]);
            float4 hp = *reinterpret_cast<const float4*>(&sHp[row_l * 64 + c]);

            float hv[4];
            const float* sr = &Sr.x; const float* sz = &Sz.x; const float* sn = &Sn.x;
            const float* gr = &Gr.x; const float* gz = &Gz.x; const float* gn = &Gn.x;
            const float* p1 = &br1.x; const float* p2 = &bz1.x; const float* p3 = &bn1.x;
            const float* p4 = &br2.x; const float* p5 = &bz2.x; const float* p6 = &bn2.x;
            const float* ph = &hp.x;
            #pragma unroll
            for (int e = 0; e < 4; e++) {
                float r = sigf(fmaf(m, sr[e] + gr[e], p1[e] + p4[e]));
                float z = sigf(fmaf(m, sz[e] + gz[e], p2[e] + p5[e]));
                float n = tanhf(fmaf(m, gn[e], p3[e]) + r * fmaf(m, sn[e], p6[e]));
                hv[e] = fmaf(z, fmaf(m, ph[e], -n), n);   // n + z*(m*h - n)
            }
            float4 o = make_float4(hv[0], hv[1], hv[2], hv[3]);
            *reinterpret_cast<float4*>(o1 + q * 4) = o;
            if (o2) *reinterpret_cast<float4*>(o2 + q * 4) = o;
            uint4 oc = make_uint4(f2tf32(hv[0]), f2tf32(hv[1]), f2tf32(hv[2]), f2tf32(hv[3]));
            *reinterpret_cast<uint4*>(oa + q * 4) = oc;
        }
    }
}

// ---------------- host ----------------
extern "C" void kernel_launch(void* const* d_in, const int* in_sizes, int n_in,
                              void* d_out, int out_size) {
    const float* hxs   = (const float*)d_in[0];
    const float* masks = (const float*)d_in[2];
    const float* pact  = (const float*)d_in[3];
    const float* W_ih  = (const float*)d_in[4];
    const float* W_hh  = (const float*)d_in[5];
    const float* b_ih  = (const float*)d_in[6];
    const float* b_hh  = (const float*)d_in[7];
    float* out = (float*)d_out;

    static bool attr_set = false;
    if (!attr_set) {
        cudaFuncSetAttribute(gi_kernel, cudaFuncAttributeMaxDynamicSharedMemorySize,
                             2 * 128 * GI_SST * 4);
        cudaFuncSetAttribute(gru_step, cudaFuncAttributeMaxDynamicSharedMemorySize,
                             SMEM_STEP);
        attr_set = true;
    }

    // Resolve device addresses of __device__ symbols.
    static float* hA0 = nullptr;
    static float* gGi = nullptr;
    if (!hA0) cudaGetSymbolAddress((void**)&hA0, g_hA);
    if (!gGi) cudaGetSymbolAddress((void**)&gGi, g_Gi);

    // 1) weight/hxs prep
    prep_kernel<<<(G3 * HH + 255) / 256, 256>>>(W_hh, W_ih, hxs);

    // 2) Gi = X @ W_ih^T for all T*N rows
    {
        dim3 grid(G3 / 128, (TT * NN) / 128);    // (12, 1024)
        gi_kernel<<<grid, 256, 2 * 128 * GI_SST * 4>>>(pact);
    }

    // 3) 128 sequential GRU steps
    const size_t stepElems = (size_t)NN * HH;
    const bool has_tail = (size_t)out_size >= (size_t)TT * stepElems + stepElems;

    dim3 grid(8, NN / 64);                       // (8, 16) = 128 CTAs
    for (int tstep = 0; tstep < TT; tstep++) {
        const float* h_prev = (tstep == 0) ? hxs : out + (size_t)(tstep - 1) * stepElems;
        float* h_out  = out + (size_t)tstep * stepElems;
        float* h_out2 = (tstep == TT - 1 && has_tail) ? out + (size_t)TT * stepElems
                                                      : nullptr;
        const float* hA_cur  = hA0 + (size_t)(tstep & 1) * NN * HH;
        float*       hA_next = hA0 + (size_t)((tstep + 1) & 1) * NN * HH;
        gru_step<<<grid, NTH, SMEM_STEP>>>(
            hA_cur, hA_next, h_prev,
            masks + (size_t)tstep * NN,
            gGi + (size_t)tstep * NN * G3,
            b_ih, b_hh, h_out, h_out2);
    }
}

// round 6
// speedup vs baseline: 1.3079x; 1.3079x over previous
#include <cuda_runtime.h>
#include <math.h>
#include <stdint.h>

// ---------------- problem dims ----------------
#define TT 128
#define NN 1024
#define HH 512
#define II 64
#define G3 1536

// step-kernel tiling: grid (16 strips x 8 rowblocks), CTA tile = 128 rows x 32 hcols
#define NSTRIP 16
#define NKSTG 16          // 512 K / 32
#define NTH 512

// ---------------- device scratch ----------------
// weights: [strip][kstage][96 gate-rows][32 k]  (k XOR-swizzled by 8*(row&3))
__device__ float g_Whh2[NSTRIP * NKSTG * 96 * 32];
// input weights for gi: [1536][64] tf32
__device__ float g_Wih_t[G3 * II];
// h (A operand, tf32): ping-pong [2][kstage][1024 rows][32 k] (swizzled)
__device__ float g_hA2[2][NKSTG * NN * 32];
// Gi: [T][strip][1024 rows][96 gate-cols]
__device__ float g_Gi[(size_t)TT * NSTRIP * NN * 96];

// ---------------- helpers ----------------
__device__ __forceinline__ uint32_t f2tf32(float f) {
    uint32_t r;
    asm("cvt.rna.tf32.f32 %0, %1;" : "=r"(r) : "f"(f));
    return r;
}
__device__ __forceinline__ uint32_t smem_u32(const void* p) {
    uint32_t a;
    asm("{ .reg .u64 t; cvta.to.shared.u64 t, %1; cvt.u32.u64 %0, t; }" : "=r"(a) : "l"(p));
    return a;
}
__device__ __forceinline__ float sigf(float x) { return 1.0f / (1.0f + __expf(-x)); }

#define CP_ASYNC16(dst, src) \
    asm volatile("cp.async.cg.shared.global [%0], [%1], 16;" :: "r"(dst), "l"(src))
#define CP_COMMIT() asm volatile("cp.async.commit_group;" ::: "memory")

#define MBARRIER_INIT(addr, cnt) \
    asm volatile("mbarrier.init.shared.b64 [%0], %1;" :: "r"(addr), "r"(cnt) : "memory")
#define MBARRIER_EXPECT_TX(addr, tx) \
    asm volatile("mbarrier.arrive.expect_tx.shared.b64 _, [%0], %1;" \
                 :: "r"(addr), "r"(tx) : "memory")
#define MBARRIER_WAIT_PARITY(mbar_addr, phase_parity) do {                                 \
    uint32_t _mbar = (uint32_t)(mbar_addr);                                                \
    uint32_t _parity = (uint32_t)(phase_parity);                                           \
    uint32_t _done;                                                                        \
    asm volatile(                                                                          \
        "{\n\t.reg .pred p;\n\t"                                                           \
        "mbarrier.try_wait.parity.acquire.cta.shared::cta.b64 p, [%1], %2;\n\t"            \
        "selp.b32 %0, 1, 0, p;\n\t}"                                                       \
        : "=r"(_done) : "r"(_mbar), "r"(_parity) : "memory");                              \
    if (!_done) {                                                                          \
        asm volatile(                                                                      \
            "{\n\t.reg .pred P1;\n\t"                                                      \
            "WAIT_LOOP_%=:\n\t"                                                            \
            "mbarrier.try_wait.parity.acquire.cta.shared::cta.b64 P1, [%0], %1, 0x989680;\n\t" \
            "@P1 bra.uni WAIT_DONE_%=;\n\t"                                                \
            "bra.uni WAIT_LOOP_%=;\n\t"                                                    \
            "WAIT_DONE_%=:\n\t}"                                                           \
            :: "r"(_mbar), "r"(_parity) : "memory");                                       \
    }                                                                                      \
} while (0)

// 1D bulk copy global -> shared, completes on mbarrier (UBLKCP; sm_90+ generic)
#define BULK_G2S(dst_smem, src_gmem, bytes, mbar) \
    asm volatile("cp.async.bulk.shared::cluster.global.mbarrier::complete_tx::bytes " \
                 "[%0], [%1], %2, [%3];" \
                 :: "r"(dst_smem), "l"(src_gmem), "r"(bytes), "r"(mbar) : "memory")

__device__ __forceinline__ void mma_tf32(float (&c)[4], const uint32_t (&a)[4],
                                         const uint32_t (&b)[2]) {
    asm volatile(
        "mma.sync.aligned.m16n8k8.row.col.f32.tf32.tf32.f32 "
        "{%0,%1,%2,%3}, {%4,%5,%6,%7}, {%8,%9}, {%0,%1,%2,%3};"
        : "+f"(c[0]), "+f"(c[1]), "+f"(c[2]), "+f"(c[3])
        : "r"(a[0]), "r"(a[1]), "r"(a[2]), "r"(a[3]), "r"(b[0]), "r"(b[1]));
}

// ================= prep: layouts + tf32 rounding =================
__global__ void prep_kernel(const float* __restrict__ W_hh,
                            const float* __restrict__ W_ih,
                            const float* __restrict__ hxs) {
    int idx = blockIdx.x * blockDim.x + threadIdx.x;
    if (idx < G3 * HH) {                         // W_hh[r][k]
        int r = idx >> 9, k = idx & 511;
        int gg = r >> 9, u = r & 511, s = u >> 5, c = u & 31;
        int cr = gg * 32 + c;                    // gate-major smem row 0..95
        int kst = k >> 5, kk = k & 31;
        int dst = ((s * NKSTG + kst) * 96 + cr) * 32 + (kk ^ (8 * (cr & 3)));
        g_Whh2[dst] = __uint_as_float(f2tf32(W_hh[idx]));
    }
    if (idx < G3 * II) g_Wih_t[idx] = __uint_as_float(f2tf32(W_ih[idx]));
    if (idx < NN * HH) {                          // hxs[n][k] -> g_hA2[0]
        int n = idx >> 9, k = idx & 511;
        int kst = k >> 5, kk = k & 31;
        g_hA2[0][(kst * NN + n) * 32 + (kk ^ (8 * (n & 3)))] =
            __uint_as_float(f2tf32(hxs[idx]));
    }
}

// ================= Gi precompute: [T][strip][1024][96] =================
#define GI_SST 68
__global__ __launch_bounds__(256, 1)
void gi_kernel(const float* __restrict__ X) {
    extern __shared__ float sm[];
    float* Xs = sm;                    // [128][GI_SST]
    float* Ws = sm + 128 * GI_SST;     // [128][GI_SST]
    const int tid = threadIdx.x;
    const int rb = blockIdx.y * 128;   // global row (t*1024+n)
    const int cb = blockIdx.x * 128;   // global gate col

    #pragma unroll
    for (int it = 0; it < 8; it++) {
        int id = it * 256 + tid;
        int row = id >> 4, c4 = (id & 15) * 4;
        float4 v = *reinterpret_cast<const float4*>(X + (size_t)(rb + row) * II + c4);
        uint4 o = make_uint4(f2tf32(v.x), f2tf32(v.y), f2tf32(v.z), f2tf32(v.w));
        *reinterpret_cast<uint4*>(Xs + row * GI_SST + c4) = o;
        float4 w = *reinterpret_cast<const float4*>(g_Wih_t + (size_t)(cb + row) * II + c4);
        *reinterpret_cast<float4*>(Ws + row * GI_SST + c4) = w;
    }
    __syncthreads();

    const int w = tid >> 5, lane = tid & 31, g = lane >> 2, t = lane & 3;
    const int wr = w & 3, wc = w >> 2;
    float acc[2][8][4];
    #pragma unroll
    for (int sl = 0; sl < 2; sl++)
        #pragma unroll
        for (int j = 0; j < 8; j++)
            #pragma unroll
            for (int q = 0; q < 4; q++) acc[sl][j][q] = 0.0f;

    #pragma unroll
    for (int k8 = 0; k8 < 8; k8++) {
        const int kb = k8 * 8;
        uint32_t a[2][4], b[8][2];
        #pragma unroll
        for (int sl = 0; sl < 2; sl++) {
            int m0 = wr * 32 + sl * 16;
            a[sl][0] = __float_as_uint(Xs[(m0 + g) * GI_SST + kb + t]);
            a[sl][1] = __float_as_uint(Xs[(m0 + 8 + g) * GI_SST + kb + t]);
            a[sl][2] = __float_as_uint(Xs[(m0 + g) * GI_SST + kb + t + 4]);
            a[sl][3] = __float_as_uint(Xs[(m0 + 8 + g) * GI_SST + kb + t + 4]);
        }
        #pragma unroll
        for (int j = 0; j < 8; j++) {
            int n0 = wc * 64 + j * 8;
            b[j][0] = __float_as_uint(Ws[(n0 + g) * GI_SST + kb + t]);
            b[j][1] = __float_as_uint(Ws[(n0 + g) * GI_SST + kb + t + 4]);
        }
        #pragma unroll
        for (int sl = 0; sl < 2; sl++)
            #pragma unroll
            for (int j = 0; j < 8; j++) mma_tf32(acc[sl][j], a[sl], b[j]);
    }

    // store: global row R = rb+..., col c -> [t][strip][n][g*32+cl]
    #pragma unroll
    for (int sl = 0; sl < 2; sl++) {
        #pragma unroll
        for (int j = 0; j < 8; j++) {
            int row = rb + wr * 32 + sl * 16 + g;
            int col = cb + wc * 64 + j * 8 + 2 * t;
            int tt = row >> 10, n = row & 1023;
            int gg = col >> 9, hcol = col & 511, s = hcol >> 5, cl = hcol & 31;
            size_t base0 = (((size_t)tt * NSTRIP + s) * NN + n) * 96 + gg * 32 + cl;
            *reinterpret_cast<float2*>(g_Gi + base0) =
                make_float2(acc[sl][j][0], acc[sl][j][1]);
            size_t base1 = (((size_t)tt * NSTRIP + s) * NN + (n + 8)) * 96 + gg * 32 + cl;
            *reinterpret_cast<float2*>(g_Gi + base1) =
                make_float2(acc[sl][j][2], acc[sl][j][3]);
        }
    }
}

// ================= per-step kernel =================
#define NBUF 4
#define A_STG_B 16384                  // 128 rows x 32 k x 4
#define B_STG_B 12288                  // 96 rows x 32 k x 4
#define STG_B (A_STG_B + B_STG_B)      // 28672
#define EPI_GI (NBUF * STG_B)          // 114688 : [128][96] f32 = 49152
#define EPI_HP (EPI_GI + 49152)        // [128][32] f32 = 16384
#define EPI_BI (EPI_HP + 16384)        // [96] f32
#define EPI_BH (EPI_BI + 384)          // [96] f32
#define EPI_M  (EPI_BH + 384)          // [128] f32
#define MB_OFF (EPI_M + 512)           // 5 mbarriers x 8B
#define SMEM_STEP (MB_OFF + 64)        // 182464
#define SST 100

__global__ __launch_bounds__(NTH, 1)
void gru_step(const float* __restrict__ hA,      // g_hA2 cur: [kst][1024][32]
              float* __restrict__ hA_next,
              const float* __restrict__ h_prev,  // fp32 [1024][512]
              const float* __restrict__ m_t,
              const float* __restrict__ Gi_t,    // [strip][1024][96] (this t)
              const float* __restrict__ Whh2,
              const float* __restrict__ b_ih,
              const float* __restrict__ b_hh,
              float* __restrict__ h_out,
              float* __restrict__ h_out2) {
    extern __shared__ char smem[];
    const uint32_t sbase = smem_u32(smem);
    const int tid = threadIdx.x;
    const int strip = blockIdx.x;      // 0..15
    const int rb = blockIdx.y * 128;   // 0..896

    const uint32_t mb = sbase + MB_OFF;       // full[0..3], epi at +32
    if (tid == 0) {
        #pragma unroll
        for (int i = 0; i < 4; i++) MBARRIER_INIT(mb + 8 * i, 1);
        MBARRIER_INIT(mb + 32, 1);
    }
    __syncthreads();

    const float* Bsrc = Whh2 + (size_t)strip * NKSTG * 96 * 32;

    if (tid == 0) {
        #pragma unroll
        for (int s = 0; s < NBUF; s++) {
            MBARRIER_EXPECT_TX(mb + 8 * s, STG_B);
            BULK_G2S(sbase + s * STG_B,
                     hA + ((size_t)s * NN + rb) * 32, A_STG_B, mb + 8 * s);
            BULK_G2S(sbase + s * STG_B + A_STG_B,
                     Bsrc + (size_t)s * 96 * 32, B_STG_B, mb + 8 * s);
        }
        MBARRIER_EXPECT_TX(mb + 32, 49152);
        BULK_G2S(sbase + EPI_GI,
                 Gi_t + ((size_t)strip * NN + rb) * 96, 49152, mb + 32);
    }

    // epilogue small prefetches (cp.async, own group; overlapped with mainloop)
    {
        #pragma unroll
        for (int it = 0; it < 2; it++) {       // h_prev tile 128x32
            int id = it * NTH + tid;           // 0..1023
            int row = id >> 3, q = id & 7;
            CP_ASYNC16(sbase + EPI_HP + (row * 32 + q * 4) * 4,
                       h_prev + (size_t)(rb + row) * HH + strip * 32 + q * 4);
        }
        if (tid < 24) {
            int c4 = tid * 4, gg = c4 >> 5, cl = c4 & 31;
            CP_ASYNC16(sbase + EPI_BI + c4 * 4, b_ih + gg * HH + strip * 32 + cl);
        } else if (tid < 48) {
            int c4 = (tid - 24) * 4, gg = c4 >> 5, cl = c4 & 31;
            CP_ASYNC16(sbase + EPI_BH + c4 * 4, b_hh + gg * HH + strip * 32 + cl);
        } else if (tid < 80) {
            int c4 = (tid - 48) * 4;
            CP_ASYNC16(sbase + EPI_M + c4 * 4, m_t + rb + c4);
        }
        CP_COMMIT();
    }

    const int w = tid >> 5, lane = tid & 31, g = lane >> 2, t2 = (lane & 3) * 2;
    const int wr = w & 7, wc = w >> 3;         // 8 rowgroups x 2 colgroups
    const int r0 = wr * 16 + g;
    const int sw0 = 8 * (g & 3);

    float acc[6][4];
    #pragma unroll
    for (int j = 0; j < 6; j++)
        #pragma unroll
        for (int q = 0; q < 4; q++) acc[j][q] = 0.0f;

    for (int stg = 0; stg < NKSTG; stg++) {
        MBARRIER_WAIT_PARITY(mb + 8 * (stg & 3), (stg >> 2) & 1);
        const float* As = (const float*)(smem + (stg & 3) * STG_B);
        const float* Bs = (const float*)(smem + (stg & 3) * STG_B + A_STG_B);
        #pragma unroll
        for (int k8 = 0; k8 < 4; k8++) {
            const int koff = (k8 * 8 + t2) ^ sw0;   // paired k' = 2t, 2t+1
            float2 a0 = *reinterpret_cast<const float2*>(&As[r0 * 32 + koff]);
            float2 a1 = *reinterpret_cast<const float2*>(&As[(r0 + 8) * 32 + koff]);
            uint32_t a[4] = {__float_as_uint(a0.x), __float_as_uint(a1.x),
                             __float_as_uint(a0.y), __float_as_uint(a1.y)};
            #pragma unroll
            for (int j = 0; j < 6; j++) {
                int cr = wc * 48 + j * 8 + g;        // cr&3 == g&3
                float2 bv = *reinterpret_cast<const float2*>(&Bs[cr * 32 + koff]);
                uint32_t b[2] = {__float_as_uint(bv.x), __float_as_uint(bv.y)};
                mma_tf32(acc[j], a, b);
            }
        }
        __syncthreads();
        if (tid == 0 && stg + NBUF < NKSTG) {
            const int s2 = stg + NBUF;
            MBARRIER_EXPECT_TX(mb + 8 * (stg & 3), STG_B);
            BULK_G2S(sbase + (stg & 3) * STG_B,
                     hA + ((size_t)s2 * NN + rb) * 32, A_STG_B, mb + 8 * (stg & 3));
            BULK_G2S(sbase + (stg & 3) * STG_B + A_STG_B,
                     Bsrc + (size_t)s2 * 96 * 32, B_STG_B, mb + 8 * (stg & 3));
        }
    }

    // ---- wait epilogue data; stage accs through smem ----
    MBARRIER_WAIT_PARITY(mb + 32, 0);
    asm volatile("cp.async.wait_group 0;" ::: "memory");
    __syncthreads();
    float* Ssh = (float*)smem;       // [128][SST] over pipeline buffers
    #pragma unroll
    for (int j = 0; j < 6; j++) {
        int c0 = wc * 48 + j * 8 + t2;
        *reinterpret_cast<float2*>(&Ssh[r0 * SST + c0]) = make_float2(acc[j][0], acc[j][1]);
        *reinterpret_cast<float2*>(&Ssh[(r0 + 8) * SST + c0]) =
            make_float2(acc[j][2], acc[j][3]);
    }
    __syncthreads();

    // ---- gates + mask + store: thread = 1 row x 8 cols ----
    {
        const float* sGi = (const float*)(smem + EPI_GI);
        const float* sHp = (const float*)(smem + EPI_HP);
        const float* sBi = (const float*)(smem + EPI_BI);
        const float* sBh = (const float*)(smem + EPI_BH);
        const float* sM  = (const float*)(smem + EPI_M);

        const int row_l = tid >> 2;
        const int cl0 = (tid & 3) * 8;
        const int grow = rb + row_l;
        const int gcol0 = strip * 32 + cl0;
        const float m = sM[row_l];
        float* o1 = h_out + (size_t)grow * HH + gcol0;
        float* o2 = h_out2 ? h_out2 + (size_t)grow * HH + gcol0 : nullptr;
        // hA_next: [kst=strip][row][k^8*(row&3)]
        float* oa = hA_next + ((size_t)strip * NN + grow) * 32;
        const int swr = 8 * (row_l & 3);

        #pragma unroll
        for (int q = 0; q < 2; q++) {
            const int c = cl0 + q * 4;
            float4 Sr = *reinterpret_cast<const float4*>(&Ssh[row_l * SST + c]);
            float4 Sz = *reinterpret_cast<const float4*>(&Ssh[row_l * SST + 32 + c]);
            float4 Sn = *reinterpret_cast<const float4*>(&Ssh[row_l * SST + 64 + c]);
            float4 Gr = *reinterpret_cast<const float4*>(&sGi[row_l * 96 + c]);
            float4 Gz = *reinterpret_cast<const float4*>(&sGi[row_l * 96 + 32 + c]);
            float4 Gn = *reinterpret_cast<const float4*>(&sGi[row_l * 96 + 64 + c]);
            float4 bi_r = *reinterpret_cast<const float4*>(&sBi[c]);
            float4 bi_z = *reinterpret_cast<const float4*>(&sBi[32 + c]);
            float4 bi_n = *reinterpret_cast<const float4*>(&sBi[64 + c]);
            float4 bh_r = *reinterpret_cast<const float4*>(&sBh[c]);
            float4 bh_z = *reinterpret_cast<const float4*>(&sBh[32 + c]);
            float4 bh_n = *reinterpret_cast<const float4*>(&sBh[64 + c]);
            float4 hp = *reinterpret_cast<const float4*>(&sHp[row_l * 32 + c]);

            float hv[4];
            const float* sr = &Sr.x; const float* sz = &Sz.x; const float* sn = &Sn.x;
            const float* gr = &Gr.x; const float* gz = &Gz.x; const float* gn = &Gn.x;
            const float* p1 = &bi_r.x; const float* p2 = &bi_z.x; const float* p3 = &bi_n.x;
            const float* p4 = &bh_r.x; const float* p5 = &bh_z.x; const float* p6 = &bh_n.x;
            const float* ph = &hp.x;
            #pragma unroll
            for (int e = 0; e < 4; e++) {
                float r = sigf(fmaf(m, sr[e] + gr[e], p1[e] + p4[e]));
                float z = sigf(fmaf(m, sz[e] + gz[e], p2[e] + p5[e]));
                float n = tanhf(fmaf(m, gn[e], p3[e]) + r * fmaf(m, sn[e], p6[e]));
                hv[e] = fmaf(z, fmaf(m, ph[e], -n), n);
            }
            float4 o = make_float4(hv[0], hv[1], hv[2], hv[3]);
            *reinterpret_cast<float4*>(o1 + q * 4) = o;
            if (o2) *reinterpret_cast<float4*>(o2 + q * 4) = o;
            uint4 oc = make_uint4(f2tf32(hv[0]), f2tf32(hv[1]), f2tf32(hv[2]), f2tf32(hv[3]));
            *reinterpret_cast<uint4*>(oa + (c ^ swr)) = oc;
        }
    }
}

// ---------------- host ----------------
extern "C" void kernel_launch(void* const* d_in, const int* in_sizes, int n_in,
                              void* d_out, int out_size) {
    const float* hxs   = (const float*)d_in[0];
    const float* masks = (const float*)d_in[2];
    const float* pact  = (const float*)d_in[3];
    const float* W_ih  = (const float*)d_in[4];
    const float* W_hh  = (const float*)d_in[5];
    const float* b_ih  = (const float*)d_in[6];
    const float* b_hh  = (const float*)d_in[7];
    float* out = (float*)d_out;

    static bool attr_set = false;
    if (!attr_set) {
        cudaFuncSetAttribute(gi_kernel, cudaFuncAttributeMaxDynamicSharedMemorySize,
                             2 * 128 * GI_SST * 4);
        cudaFuncSetAttribute(gru_step, cudaFuncAttributeMaxDynamicSharedMemorySize,
                             SMEM_STEP);
        attr_set = true;
    }

    static float* hA0 = nullptr;
    static float* gGi = nullptr;
    static float* gW2 = nullptr;
    if (!hA0) cudaGetSymbolAddress((void**)&hA0, g_hA2);
    if (!gGi) cudaGetSymbolAddress((void**)&gGi, g_Gi);
    if (!gW2) cudaGetSymbolAddress((void**)&gW2, g_Whh2);

    // 1) prep
    prep_kernel<<<(G3 * HH + 255) / 256, 256>>>(W_hh, W_ih, hxs);

    // 2) Gi
    {
        dim3 grid(G3 / 128, (TT * NN) / 128);
        gi_kernel<<<grid, 256, 2 * 128 * GI_SST * 4>>>(pact);
    }

    // 3) sequential steps
    const size_t stepElems = (size_t)NN * HH;
    const size_t hASz = (size_t)NKSTG * NN * 32;
    const bool has_tail = (size_t)out_size >= (size_t)TT * stepElems + stepElems;

    dim3 grid(NSTRIP, NN / 128);                 // (16, 8) = 128 CTAs
    for (int tstep = 0; tstep < TT; tstep++) {
        const float* h_prev = (tstep == 0) ? hxs : out + (size_t)(tstep - 1) * stepElems;
        float* h_out  = out + (size_t)tstep * stepElems;
        float* h_out2 = (tstep == TT - 1 && has_tail) ? out + (size_t)TT * stepElems
                                                      : nullptr;
        const float* hA_cur  = hA0 + (size_t)(tstep & 1) * hASz;
        float*       hA_next = hA0 + (size_t)((tstep + 1) & 1) * hASz;
        gru_step<<<grid, NTH, SMEM_STEP>>>(
            hA_cur, hA_next, h_prev,
            masks + (size_t)tstep * NN,
            gGi + (size_t)tstep * NSTRIP * NN * 96,
            gW2, b_ih, b_hh, h_out, h_out2);
    }
}